// round 2
// baseline (speedup 1.0000x reference)
#include <cuda_runtime.h>
#include <math.h>

#define S_LEN 2048
#define D_MODEL 2048
#define NHEAD 32
#define HDIM 64
#define FF_DIM 8192
#define QKV_N (3 * D_MODEL)

// ---------------- scratch (static device globals; no allocation) ----------------
__device__ float g_h  [S_LEN * D_MODEL];    // ln1 output
__device__ float g_qkv[S_LEN * QKV_N];      // fused qkv
__device__ float g_ctx[S_LEN * D_MODEL];    // attention context
__device__ float g_res[S_LEN * D_MODEL];    // x + attn_out
__device__ float g_h2 [S_LEN * D_MODEL];    // ln2 output
__device__ float g_mlp[S_LEN * FF_DIM];     // gelu(h2 @ w1 + b1)

// ---------------- layernorm: one block per row, 2048 cols ----------------
__global__ __launch_bounds__(256)
void ln_kernel(const float* __restrict__ in, const float* __restrict__ gam,
               const float* __restrict__ bet, float* __restrict__ out)
{
    int row = blockIdx.x;
    int tid = threadIdx.x;
    const float* r = in + (size_t)row * D_MODEL;
    float v[8];
    float s = 0.f, s2 = 0.f;
#pragma unroll
    for (int i = 0; i < 8; i++) {
        v[i] = r[tid + i * 256];
        s  += v[i];
        s2 += v[i] * v[i];
    }
#pragma unroll
    for (int o = 16; o; o >>= 1) {
        s  += __shfl_xor_sync(0xffffffffu, s,  o);
        s2 += __shfl_xor_sync(0xffffffffu, s2, o);
    }
    __shared__ float sh0[8], sh1[8];
    if ((tid & 31) == 0) { sh0[tid >> 5] = s; sh1[tid >> 5] = s2; }
    __syncthreads();
    s = 0.f; s2 = 0.f;
#pragma unroll
    for (int i = 0; i < 8; i++) { s += sh0[i]; s2 += sh1[i]; }
    float mean = s * (1.f / D_MODEL);
    float var  = s2 * (1.f / D_MODEL) - mean * mean;
    float rstd = rsqrtf(var + 1e-5f);
    float* w = out + (size_t)row * D_MODEL;
#pragma unroll
    for (int i = 0; i < 8; i++) {
        int c = tid + i * 256;
        w[c] = (v[i] - mean) * rstd * gam[c] + bet[c];
    }
}

// ---------------- SGEMM: C[M,N] = A[M,K] @ B[K,N], fused epilogues ----------------
// EPI 0: C = acc + bias
// EPI 1: C = resid + acc + bias
// EPI 2: C = gelu_exact(acc + bias)
#define TM 128
#define TN 128
#define TK 16

template<int EPI>
__global__ __launch_bounds__(256, 2)
void gemm_kernel(const float* __restrict__ A, const float* __restrict__ B,
                 const float* __restrict__ bias, const float* __restrict__ resid,
                 float* __restrict__ C, int M, int N, int K)
{
    __shared__ float As[TK][TM + 4];   // transposed A tile, pad 4 (row = 528B, 16B aligned)
    __shared__ float Bs[TK][TN];

    int tid = threadIdx.x;
    int tx = tid & 15, ty = tid >> 4;
    int m0 = blockIdx.y * TM, n0 = blockIdx.x * TN;

    float acc[8][8];
#pragma unroll
    for (int i = 0; i < 8; i++)
#pragma unroll
        for (int j = 0; j < 8; j++) acc[i][j] = 0.f;

    const float* Ab = A + (size_t)m0 * K;
    const float* Bb = B + n0;

    for (int k0 = 0; k0 < K; k0 += TK) {
        // A tile: 128 rows x 16 k  (512 float4, 2 per thread), store transposed
#pragma unroll
        for (int t = 0; t < 2; t++) {
            int lin = tid + t * 256;
            int row = lin >> 2;
            int kq  = (lin & 3) << 2;
            float4 v = *(const float4*)(Ab + (size_t)row * K + k0 + kq);
            As[kq + 0][row] = v.x; As[kq + 1][row] = v.y;
            As[kq + 2][row] = v.z; As[kq + 3][row] = v.w;
        }
        // B tile: 16 rows x 128 n
#pragma unroll
        for (int t = 0; t < 2; t++) {
            int lin = tid + t * 256;
            int row = lin >> 5;
            int nq  = (lin & 31) << 2;
            *(float4*)(&Bs[row][nq]) = *(const float4*)(Bb + (size_t)(k0 + row) * N + nq);
        }
        __syncthreads();
#pragma unroll
        for (int k = 0; k < TK; k++) {
            float a[8], b[8];
            *(float4*)(a)     = *(const float4*)(&As[k][ty * 8]);
            *(float4*)(a + 4) = *(const float4*)(&As[k][ty * 8 + 4]);
            *(float4*)(b)     = *(const float4*)(&Bs[k][tx * 8]);
            *(float4*)(b + 4) = *(const float4*)(&Bs[k][tx * 8 + 4]);
#pragma unroll
            for (int i = 0; i < 8; i++)
#pragma unroll
                for (int j = 0; j < 8; j++)
                    acc[i][j] = fmaf(a[i], b[j], acc[i][j]);
        }
        __syncthreads();
    }

#pragma unroll
    for (int i = 0; i < 8; i++) {
        int m = m0 + ty * 8 + i;
#pragma unroll
        for (int j = 0; j < 8; j++) {
            int n = n0 + tx * 8 + j;
            float v = acc[i][j] + bias[n];
            if (EPI == 1) v += resid[(size_t)m * N + n];
            if (EPI == 2) v = 0.5f * v * (1.f + erff(v * 0.70710678118654752f));
            C[(size_t)m * N + n] = v;
        }
    }
}

// ---------------- flash attention with ALiBi + causal ----------------
// grid (S/64, H), block 256 (16x16). 64 queries x 32-key tiles, online softmax.
__global__ __launch_bounds__(256)
void attn_kernel(const float* __restrict__ qkv, const float* __restrict__ alibi,
                 float* __restrict__ ctx)
{
    __shared__ float Qs[64][65];   // transposed: Qs[d][q]
    __shared__ float Ks[64][33];   // transposed: Ks[d][k]
    __shared__ float Vs[32][68];   // natural:    Vs[k][d]
    __shared__ float Ps[64][33];   // probs:      Ps[q][k]

    int tid = threadIdx.x;
    int tx = tid & 15, ty = tid >> 4;
    int q0 = blockIdx.x * 64;
    int h  = blockIdx.y;

    const float* Qg = qkv + h * HDIM;
    const float* Kg = qkv + D_MODEL + h * HDIM;
    const float* Vg = qkv + 2 * D_MODEL + h * HDIM;
    const float* ab = alibi + (size_t)h * S_LEN;
    const float inv = 0.125f;  // 1/sqrt(64)

    // load Q tile transposed (64 rows x 64 dims)
#pragma unroll
    for (int t = 0; t < 4; t++) {
        int lin = tid + t * 256;
        int row = lin >> 4;
        int c4  = (lin & 15) << 2;
        float4 v = *(const float4*)(Qg + (size_t)(q0 + row) * QKV_N + c4);
        Qs[c4 + 0][row] = v.x; Qs[c4 + 1][row] = v.y;
        Qs[c4 + 2][row] = v.z; Qs[c4 + 3][row] = v.w;
    }

    float acc[4][4];
    float m_i[4], l_i[4];
#pragma unroll
    for (int i = 0; i < 4; i++) {
        m_i[i] = -1e30f; l_i[i] = 0.f;
#pragma unroll
        for (int j = 0; j < 4; j++) acc[i][j] = 0.f;
    }

    for (int k0 = 0; k0 < q0 + 64; k0 += 32) {
        __syncthreads();   // prior PV reads done before overwriting K/V
        // load K (transposed) + V (natural): 32 rows x 64 dims each
#pragma unroll
        for (int t = 0; t < 2; t++) {
            int lin = tid + t * 256;
            int row = lin >> 4;
            int c4  = (lin & 15) << 2;
            float4 v = *(const float4*)(Kg + (size_t)(k0 + row) * QKV_N + c4);
            Ks[c4 + 0][row] = v.x; Ks[c4 + 1][row] = v.y;
            Ks[c4 + 2][row] = v.z; Ks[c4 + 3][row] = v.w;
            float4 w = *(const float4*)(Vg + (size_t)(k0 + row) * QKV_N + c4);
            *(float4*)(&Vs[row][c4]) = w;
        }
        __syncthreads();

        // S = Q @ K^T : each thread 4q x 2k
        float s[4][2];
#pragma unroll
        for (int i = 0; i < 4; i++) { s[i][0] = 0.f; s[i][1] = 0.f; }
#pragma unroll
        for (int d = 0; d < 64; d++) {
            float a0 = Qs[d][ty * 4 + 0], a1 = Qs[d][ty * 4 + 1];
            float a2 = Qs[d][ty * 4 + 2], a3 = Qs[d][ty * 4 + 3];
            float b0 = Ks[d][tx * 2 + 0], b1 = Ks[d][tx * 2 + 1];
            s[0][0] = fmaf(a0, b0, s[0][0]); s[0][1] = fmaf(a0, b1, s[0][1]);
            s[1][0] = fmaf(a1, b0, s[1][0]); s[1][1] = fmaf(a1, b1, s[1][1]);
            s[2][0] = fmaf(a2, b0, s[2][0]); s[2][1] = fmaf(a2, b1, s[2][1]);
            s[3][0] = fmaf(a3, b0, s[3][0]); s[3][1] = fmaf(a3, b1, s[3][1]);
        }

        // scale + alibi + causal mask, row max
        float rmax[4];
#pragma unroll
        for (int i = 0; i < 4; i++) {
            int qg = q0 + ty * 4 + i;
            float mx = -1e30f;
#pragma unroll
            for (int j = 0; j < 2; j++) {
                int kg = k0 + tx * 2 + j;
                float val = (kg <= qg) ? (s[i][j] + ab[kg]) * inv : -1e30f;
                s[i][j] = val;
                mx = fmaxf(mx, val);
            }
            rmax[i] = mx;
        }
#pragma unroll
        for (int o = 1; o < 16; o <<= 1) {
#pragma unroll
            for (int i = 0; i < 4; i++)
                rmax[i] = fmaxf(rmax[i], __shfl_xor_sync(0xffffffffu, rmax[i], o));
        }

        // online softmax update + write P
#pragma unroll
        for (int i = 0; i < 4; i++) {
            float mnew = fmaxf(m_i[i], rmax[i]);
            float sc = expf(m_i[i] - mnew);
            float p0 = expf(s[i][0] - mnew);
            float p1 = expf(s[i][1] - mnew);
            Ps[ty * 4 + i][tx * 2 + 0] = p0;
            Ps[ty * 4 + i][tx * 2 + 1] = p1;
            float ps = p0 + p1;
#pragma unroll
            for (int o = 1; o < 16; o <<= 1)
                ps += __shfl_xor_sync(0xffffffffu, ps, o);
            l_i[i] = l_i[i] * sc + ps;
            m_i[i] = mnew;
            acc[i][0] *= sc; acc[i][1] *= sc; acc[i][2] *= sc; acc[i][3] *= sc;
        }
        __syncthreads();   // Ps visible

        // O += P @ V : each thread 4q x 4d
#pragma unroll
        for (int kk = 0; kk < 32; kk++) {
            float p0 = Ps[ty * 4 + 0][kk], p1 = Ps[ty * 4 + 1][kk];
            float p2 = Ps[ty * 4 + 2][kk], p3 = Ps[ty * 4 + 3][kk];
            float v0 = Vs[kk][tx * 4 + 0], v1 = Vs[kk][tx * 4 + 1];
            float v2 = Vs[kk][tx * 4 + 2], v3 = Vs[kk][tx * 4 + 3];
            acc[0][0] = fmaf(p0, v0, acc[0][0]); acc[0][1] = fmaf(p0, v1, acc[0][1]);
            acc[0][2] = fmaf(p0, v2, acc[0][2]); acc[0][3] = fmaf(p0, v3, acc[0][3]);
            acc[1][0] = fmaf(p1, v0, acc[1][0]); acc[1][1] = fmaf(p1, v1, acc[1][1]);
            acc[1][2] = fmaf(p1, v2, acc[1][2]); acc[1][3] = fmaf(p1, v3, acc[1][3]);
            acc[2][0] = fmaf(p2, v0, acc[2][0]); acc[2][1] = fmaf(p2, v1, acc[2][1]);
            acc[2][2] = fmaf(p2, v2, acc[2][2]); acc[2][3] = fmaf(p2, v3, acc[2][3]);
            acc[3][0] = fmaf(p3, v0, acc[3][0]); acc[3][1] = fmaf(p3, v1, acc[3][1]);
            acc[3][2] = fmaf(p3, v2, acc[3][2]); acc[3][3] = fmaf(p3, v3, acc[3][3]);
        }
    }

    // write ctx[s][h*64 + d]
#pragma unroll
    for (int i = 0; i < 4; i++) {
        float r = 1.f / l_i[i];
        int qg = q0 + ty * 4 + i;
        float* w = ctx + (size_t)qg * D_MODEL + h * HDIM + tx * 4;
        w[0] = acc[i][0] * r; w[1] = acc[i][1] * r;
        w[2] = acc[i][2] * r; w[3] = acc[i][3] * r;
    }
}

// ---------------- launch ----------------
extern "C" void kernel_launch(void* const* d_in, const int* in_sizes, int n_in,
                              void* d_out, int out_size)
{
    const float* x     = (const float*)d_in[0];
    const float* alibi = (const float*)d_in[1];
    // d_in[2] attention_mask: causal -1e9 mask, implemented exactly via skip
    const float* ln1g  = (const float*)d_in[3];
    const float* ln1b  = (const float*)d_in[4];
    const float* ln2g  = (const float*)d_in[5];
    const float* ln2b  = (const float*)d_in[6];
    const float* wqkv  = (const float*)d_in[7];
    const float* bqkv  = (const float*)d_in[8];
    const float* wo    = (const float*)d_in[9];
    const float* bo    = (const float*)d_in[10];
    const float* w1    = (const float*)d_in[11];
    const float* b1    = (const float*)d_in[12];
    const float* w2    = (const float*)d_in[13];
    const float* b2    = (const float*)d_in[14];
    float* out = (float*)d_out;

    float *h, *qkv, *ctx, *res, *h2, *mlp;
    cudaGetSymbolAddress((void**)&h,   g_h);
    cudaGetSymbolAddress((void**)&qkv, g_qkv);
    cudaGetSymbolAddress((void**)&ctx, g_ctx);
    cudaGetSymbolAddress((void**)&res, g_res);
    cudaGetSymbolAddress((void**)&h2,  g_h2);
    cudaGetSymbolAddress((void**)&mlp, g_mlp);

    // 1. h = LN1(x)
    ln_kernel<<<S_LEN, 256>>>(x, ln1g, ln1b, h);
    // 2. qkv = h @ wqkv + bqkv
    gemm_kernel<0><<<dim3(QKV_N / TN, S_LEN / TM), 256>>>(h, wqkv, bqkv, nullptr, qkv,
                                                          S_LEN, QKV_N, D_MODEL);
    // 3. ctx = attention(q, k, v) with ALiBi + causal
    attn_kernel<<<dim3(S_LEN / 64, NHEAD), 256>>>(qkv, alibi, ctx);
    // 4. res = x + ctx @ wo + bo
    gemm_kernel<1><<<dim3(D_MODEL / TN, S_LEN / TM), 256>>>(ctx, wo, bo, x, res,
                                                            S_LEN, D_MODEL, D_MODEL);
    // 5. h2 = LN2(res)
    ln_kernel<<<S_LEN, 256>>>(res, ln2g, ln2b, h2);
    // 6. mlp = gelu(h2 @ w1 + b1)
    gemm_kernel<2><<<dim3(FF_DIM / TN, S_LEN / TM), 256>>>(h2, w1, b1, nullptr, mlp,
                                                           S_LEN, FF_DIM, D_MODEL);
    // 7. out = res + mlp @ w2 + b2
    gemm_kernel<1><<<dim3(D_MODEL / TN, S_LEN / TM), 256>>>(mlp, w2, b2, res, out,
                                                            S_LEN, D_MODEL, FF_DIM);
}

// round 4
// speedup vs baseline: 2.3138x; 2.3138x over previous
#include <cuda_runtime.h>
#include <cstdint>
#include <math.h>

#define S_LEN 2048
#define D_MODEL 2048
#define NHEAD 32
#define HDIM 64
#define FF_DIM 8192
#define QKV_N (3 * D_MODEL)

// ---------------- scratch (static device globals; no allocation) ----------------
__device__ float g_h  [S_LEN * D_MODEL];
__device__ float g_qkv[S_LEN * QKV_N];
__device__ float g_ctx[S_LEN * D_MODEL];
__device__ float g_res[S_LEN * D_MODEL];
__device__ float g_h2 [S_LEN * D_MODEL];
__device__ float g_mlp[S_LEN * FF_DIM];

// ================= helpers =================
__device__ __forceinline__ uint32_t smem_u32(const void* p) {
    uint32_t a;
    asm("{ .reg .u64 t; cvta.to.shared.u64 t, %1; cvt.u32.u64 %0, t; }" : "=r"(a) : "l"(p));
    return a;
}
__device__ __forceinline__ void cpa16(uint32_t dst, const float* src) {
    asm volatile("cp.async.cg.shared.global [%0], [%1], 16;" :: "r"(dst), "l"(src));
}
#define CP_COMMIT() asm volatile("cp.async.commit_group;" ::: "memory")
#define CP_WAIT(n)  asm volatile("cp.async.wait_group %0;" :: "n"(n) : "memory")

__device__ __forceinline__ uint32_t f2tf32(float f) {
    uint32_t u;
    asm("cvt.rna.tf32.f32 %0, %1;" : "=r"(u) : "f"(f));
    return u;
}
__device__ __forceinline__ void mma_tf32(float* d, const uint32_t* a, const uint32_t* b) {
    asm volatile(
        "mma.sync.aligned.m16n8k8.row.col.f32.tf32.tf32.f32 "
        "{%0,%1,%2,%3}, {%4,%5,%6,%7}, {%8,%9}, {%0,%1,%2,%3};"
        : "+f"(d[0]), "+f"(d[1]), "+f"(d[2]), "+f"(d[3])
        : "r"(a[0]), "r"(a[1]), "r"(a[2]), "r"(a[3]), "r"(b[0]), "r"(b[1]));
}

// ================= tf32 tensor-core GEMM =================
// C[M,N] = A[M,K] @ B[K,N].  128x128 block tile, K-chunk 32, double-buffered cp.async.
// 8 warps = 4(m) x 2(n); warp tile 32x64; mma m16n8k8.
// EPI 0: +bias   EPI 1: +bias+resid   EPI 2: gelu_exact(+bias)
#define AS_STRIDE 36                    // 32 k + pad 4  (floats)
#define BS_STRIDE 136                   // 128 n + pad 8 (floats)
#define A_STAGE (128 * AS_STRIDE)       // floats
#define B_STAGE (32 * BS_STRIDE)        // floats
#define GEMM_SMEM ((2 * A_STAGE + 2 * B_STAGE) * 4)

template<int EPI>
__global__ __launch_bounds__(256)
void mma_gemm(const float* __restrict__ A, const float* __restrict__ B,
              const float* __restrict__ bias, const float* __restrict__ resid,
              float* __restrict__ C, int M, int N, int K)
{
    extern __shared__ float sm[];
    float* sA = sm;                     // [2][128][AS_STRIDE]
    float* sB = sm + 2 * A_STAGE;       // [2][32][BS_STRIDE]
    uint32_t sAu = smem_u32(sA);
    uint32_t sBu = smem_u32(sB);

    int tid = threadIdx.x;
    int lane = tid & 31, wid = tid >> 5;
    int g = lane >> 2, t = lane & 3;
    int wm = wid & 3, wn = wid >> 2;
    int m0 = blockIdx.y * 128, n0 = blockIdx.x * 128;

    float acc[2][8][4];
#pragma unroll
    for (int i = 0; i < 2; i++)
#pragma unroll
        for (int j = 0; j < 8; j++)
#pragma unroll
            for (int c = 0; c < 4; c++) acc[i][j][c] = 0.f;

    const int T = K / 32;

    // ---- stage loaders ----
    auto load_stage = [&](int st, int k0) {
        uint32_t ab = sAu + (uint32_t)st * A_STAGE * 4;
        uint32_t bb = sBu + (uint32_t)st * B_STAGE * 4;
#pragma unroll
        for (int q = 0; q < 4; q++) {       // A: 128 rows x 32 k
            int id = tid + q * 256;
            int m = id >> 3, c = id & 7;
            cpa16(ab + (uint32_t)(m * AS_STRIDE + c * 4) * 4,
                  A + (size_t)(m0 + m) * K + k0 + c * 4);
        }
#pragma unroll
        for (int q = 0; q < 4; q++) {       // B: 32 k x 128 n (natural)
            int id = tid + q * 256;
            int k = id >> 5, c = id & 31;
            cpa16(bb + (uint32_t)(k * BS_STRIDE + c * 4) * 4,
                  B + (size_t)(k0 + k) * N + n0 + c * 4);
        }
        CP_COMMIT();
    };

    load_stage(0, 0);

    for (int i = 0; i < T; i++) {
        int st = i & 1;
        if (i + 1 < T) {
            load_stage(st ^ 1, (i + 1) * 32);
            CP_WAIT(1);
        } else {
            CP_WAIT(0);
        }
        __syncthreads();

        const float* a_st = sA + st * A_STAGE;
        const float* b_st = sB + st * B_STAGE;
#pragma unroll
        for (int ks = 0; ks < 4; ks++) {
            int kb = ks * 8;
            uint32_t af[2][4];
#pragma unroll
            for (int mi = 0; mi < 2; mi++) {
                int r = wm * 32 + mi * 16 + g;
                af[mi][0] = f2tf32(a_st[r * AS_STRIDE + kb + t]);
                af[mi][1] = f2tf32(a_st[(r + 8) * AS_STRIDE + kb + t]);
                af[mi][2] = f2tf32(a_st[r * AS_STRIDE + kb + t + 4]);
                af[mi][3] = f2tf32(a_st[(r + 8) * AS_STRIDE + kb + t + 4]);
            }
            uint32_t bf[8][2];
#pragma unroll
            for (int nj = 0; nj < 8; nj++) {
                int cidx = wn * 64 + nj * 8 + g;
                bf[nj][0] = f2tf32(b_st[(kb + t) * BS_STRIDE + cidx]);
                bf[nj][1] = f2tf32(b_st[(kb + t + 4) * BS_STRIDE + cidx]);
            }
#pragma unroll
            for (int mi = 0; mi < 2; mi++)
#pragma unroll
                for (int nj = 0; nj < 8; nj++)
                    mma_tf32(acc[mi][nj], af[mi], bf[nj]);
        }
        __syncthreads();
    }

    // ---- epilogue ----
#pragma unroll
    for (int mi = 0; mi < 2; mi++) {
#pragma unroll
        for (int nj = 0; nj < 8; nj++) {
            int r0 = m0 + wm * 32 + mi * 16 + g;
            int c0 = n0 + wn * 64 + nj * 8 + 2 * t;
            float2 bv = *(const float2*)(bias + c0);
#pragma unroll
            for (int half = 0; half < 2; half++) {
                int r = r0 + half * 8;
                float vx = acc[mi][nj][half * 2 + 0] + bv.x;
                float vy = acc[mi][nj][half * 2 + 1] + bv.y;
                if (EPI == 1) {
                    float2 rv = *(const float2*)(resid + (size_t)r * N + c0);
                    vx += rv.x; vy += rv.y;
                }
                if (EPI == 2) {
                    vx = 0.5f * vx * (1.f + erff(vx * 0.70710678118654752f));
                    vy = 0.5f * vy * (1.f + erff(vy * 0.70710678118654752f));
                }
                float2 o = make_float2(vx, vy);
                *(float2*)(C + (size_t)r * N + c0) = o;
            }
        }
    }
}

// ---------------- layernorm ----------------
__global__ __launch_bounds__(256)
void ln_kernel(const float* __restrict__ in, const float* __restrict__ gam,
               const float* __restrict__ bet, float* __restrict__ out)
{
    int row = blockIdx.x;
    int tid = threadIdx.x;
    const float* r = in + (size_t)row * D_MODEL;
    float v[8];
    float s = 0.f, s2 = 0.f;
#pragma unroll
    for (int i = 0; i < 8; i++) {
        v[i] = r[tid + i * 256];
        s += v[i]; s2 += v[i] * v[i];
    }
#pragma unroll
    for (int o = 16; o; o >>= 1) {
        s  += __shfl_xor_sync(0xffffffffu, s,  o);
        s2 += __shfl_xor_sync(0xffffffffu, s2, o);
    }
    __shared__ float sh0[8], sh1[8];
    if ((tid & 31) == 0) { sh0[tid >> 5] = s; sh1[tid >> 5] = s2; }
    __syncthreads();
    s = 0.f; s2 = 0.f;
#pragma unroll
    for (int i = 0; i < 8; i++) { s += sh0[i]; s2 += sh1[i]; }
    float mean = s * (1.f / D_MODEL);
    float var = s2 * (1.f / D_MODEL) - mean * mean;
    float rstd = rsqrtf(var + 1e-5f);
    float* w = out + (size_t)row * D_MODEL;
#pragma unroll
    for (int i = 0; i < 8; i++) {
        int c = tid + i * 256;
        w[c] = (v[i] - mean) * rstd * gam[c] + bet[c];
    }
}

// ---------------- flash attention with ALiBi + causal ----------------
__global__ __launch_bounds__(256)
void attn_kernel(const float* __restrict__ qkv, const float* __restrict__ alibi,
                 float* __restrict__ ctx)
{
    __shared__ float Qs[64][65];
    __shared__ float Ks[64][33];
    __shared__ float Vs[32][68];
    __shared__ float Ps[64][33];

    int tid = threadIdx.x;
    int tx = tid & 15, ty = tid >> 4;
    int q0 = blockIdx.x * 64;
    int h = blockIdx.y;

    const float* Qg = qkv + h * HDIM;
    const float* Kg = qkv + D_MODEL + h * HDIM;
    const float* Vg = qkv + 2 * D_MODEL + h * HDIM;
    const float* ab = alibi + (size_t)h * S_LEN;
    const float inv = 0.125f;

#pragma unroll
    for (int t = 0; t < 4; t++) {
        int lin = tid + t * 256;
        int row = lin >> 4;
        int c4 = (lin & 15) << 2;
        float4 v = *(const float4*)(Qg + (size_t)(q0 + row) * QKV_N + c4);
        Qs[c4 + 0][row] = v.x; Qs[c4 + 1][row] = v.y;
        Qs[c4 + 2][row] = v.z; Qs[c4 + 3][row] = v.w;
    }

    float acc[4][4];
    float m_i[4], l_i[4];
#pragma unroll
    for (int i = 0; i < 4; i++) {
        m_i[i] = -1e30f; l_i[i] = 0.f;
#pragma unroll
        for (int j = 0; j < 4; j++) acc[i][j] = 0.f;
    }

    for (int k0 = 0; k0 < q0 + 64; k0 += 32) {
        __syncthreads();
#pragma unroll
        for (int t = 0; t < 2; t++) {
            int lin = tid + t * 256;
            int row = lin >> 4;
            int c4 = (lin & 15) << 2;
            float4 v = *(const float4*)(Kg + (size_t)(k0 + row) * QKV_N + c4);
            Ks[c4 + 0][row] = v.x; Ks[c4 + 1][row] = v.y;
            Ks[c4 + 2][row] = v.z; Ks[c4 + 3][row] = v.w;
            float4 w = *(const float4*)(Vg + (size_t)(k0 + row) * QKV_N + c4);
            *(float4*)(&Vs[row][c4]) = w;
        }
        __syncthreads();

        float s[4][2];
#pragma unroll
        for (int i = 0; i < 4; i++) { s[i][0] = 0.f; s[i][1] = 0.f; }
#pragma unroll
        for (int d = 0; d < 64; d++) {
            float a0 = Qs[d][ty * 4 + 0], a1 = Qs[d][ty * 4 + 1];
            float a2 = Qs[d][ty * 4 + 2], a3 = Qs[d][ty * 4 + 3];
            float b0 = Ks[d][tx * 2 + 0], b1 = Ks[d][tx * 2 + 1];
            s[0][0] = fmaf(a0, b0, s[0][0]); s[0][1] = fmaf(a0, b1, s[0][1]);
            s[1][0] = fmaf(a1, b0, s[1][0]); s[1][1] = fmaf(a1, b1, s[1][1]);
            s[2][0] = fmaf(a2, b0, s[2][0]); s[2][1] = fmaf(a2, b1, s[2][1]);
            s[3][0] = fmaf(a3, b0, s[3][0]); s[3][1] = fmaf(a3, b1, s[3][1]);
        }

        float rmax[4];
#pragma unroll
        for (int i = 0; i < 4; i++) {
            int qg = q0 + ty * 4 + i;
            float mx = -1e30f;
#pragma unroll
            for (int j = 0; j < 2; j++) {
                int kg = k0 + tx * 2 + j;
                float val = (kg <= qg) ? (s[i][j] + ab[kg]) * inv : -1e30f;
                s[i][j] = val;
                mx = fmaxf(mx, val);
            }
            rmax[i] = mx;
        }
#pragma unroll
        for (int o = 1; o < 16; o <<= 1) {
#pragma unroll
            for (int i = 0; i < 4; i++)
                rmax[i] = fmaxf(rmax[i], __shfl_xor_sync(0xffffffffu, rmax[i], o));
        }

#pragma unroll
        for (int i = 0; i < 4; i++) {
            float mnew = fmaxf(m_i[i], rmax[i]);
            float sc = expf(m_i[i] - mnew);
            float p0 = expf(s[i][0] - mnew);
            float p1 = expf(s[i][1] - mnew);
            Ps[ty * 4 + i][tx * 2 + 0] = p0;
            Ps[ty * 4 + i][tx * 2 + 1] = p1;
            float ps = p0 + p1;
#pragma unroll
            for (int o = 1; o < 16; o <<= 1)
                ps += __shfl_xor_sync(0xffffffffu, ps, o);
            l_i[i] = l_i[i] * sc + ps;
            m_i[i] = mnew;
            acc[i][0] *= sc; acc[i][1] *= sc; acc[i][2] *= sc; acc[i][3] *= sc;
        }
        __syncthreads();

#pragma unroll
        for (int kk = 0; kk < 32; kk++) {
            float p0 = Ps[ty * 4 + 0][kk], p1 = Ps[ty * 4 + 1][kk];
            float p2 = Ps[ty * 4 + 2][kk], p3 = Ps[ty * 4 + 3][kk];
            float v0 = Vs[kk][tx * 4 + 0], v1 = Vs[kk][tx * 4 + 1];
            float v2 = Vs[kk][tx * 4 + 2], v3 = Vs[kk][tx * 4 + 3];
            acc[0][0] = fmaf(p0, v0, acc[0][0]); acc[0][1] = fmaf(p0, v1, acc[0][1]);
            acc[0][2] = fmaf(p0, v2, acc[0][2]); acc[0][3] = fmaf(p0, v3, acc[0][3]);
            acc[1][0] = fmaf(p1, v0, acc[1][0]); acc[1][1] = fmaf(p1, v1, acc[1][1]);
            acc[1][2] = fmaf(p1, v2, acc[1][2]); acc[1][3] = fmaf(p1, v3, acc[1][3]);
            acc[2][0] = fmaf(p2, v0, acc[2][0]); acc[2][1] = fmaf(p2, v1, acc[2][1]);
            acc[2][2] = fmaf(p2, v2, acc[2][2]); acc[2][3] = fmaf(p2, v3, acc[2][3]);
            acc[3][0] = fmaf(p3, v0, acc[3][0]); acc[3][1] = fmaf(p3, v1, acc[3][1]);
            acc[3][2] = fmaf(p3, v2, acc[3][2]); acc[3][3] = fmaf(p3, v3, acc[3][3]);
        }
    }

#pragma unroll
    for (int i = 0; i < 4; i++) {
        float r = 1.f / l_i[i];
        int qg = q0 + ty * 4 + i;
        float* w = ctx + (size_t)qg * D_MODEL + h * HDIM + tx * 4;
        w[0] = acc[i][0] * r; w[1] = acc[i][1] * r;
        w[2] = acc[i][2] * r; w[3] = acc[i][3] * r;
    }
}

// ---------------- launch ----------------
extern "C" void kernel_launch(void* const* d_in, const int* in_sizes, int n_in,
                              void* d_out, int out_size)
{
    const float* x     = (const float*)d_in[0];
    const float* alibi = (const float*)d_in[1];
    const float* ln1g  = (const float*)d_in[3];
    const float* ln1b  = (const float*)d_in[4];
    const float* ln2g  = (const float*)d_in[5];
    const float* ln2b  = (const float*)d_in[6];
    const float* wqkv  = (const float*)d_in[7];
    const float* bqkv  = (const float*)d_in[8];
    const float* wo    = (const float*)d_in[9];
    const float* bo    = (const float*)d_in[10];
    const float* w1    = (const float*)d_in[11];
    const float* b1    = (const float*)d_in[12];
    const float* w2    = (const float*)d_in[13];
    const float* b2    = (const float*)d_in[14];
    float* out = (float*)d_out;

    float *h, *qkv, *ctx, *res, *h2, *mlp;
    cudaGetSymbolAddress((void**)&h,   g_h);
    cudaGetSymbolAddress((void**)&qkv, g_qkv);
    cudaGetSymbolAddress((void**)&ctx, g_ctx);
    cudaGetSymbolAddress((void**)&res, g_res);
    cudaGetSymbolAddress((void**)&h2,  g_h2);
    cudaGetSymbolAddress((void**)&mlp, g_mlp);

    cudaFuncSetAttribute(mma_gemm<0>, cudaFuncAttributeMaxDynamicSharedMemorySize, GEMM_SMEM);
    cudaFuncSetAttribute(mma_gemm<1>, cudaFuncAttributeMaxDynamicSharedMemorySize, GEMM_SMEM);
    cudaFuncSetAttribute(mma_gemm<2>, cudaFuncAttributeMaxDynamicSharedMemorySize, GEMM_SMEM);

    // 1. h = LN1(x)
    ln_kernel<<<S_LEN, 256>>>(x, ln1g, ln1b, h);
    // 2. qkv = h @ wqkv + bqkv
    mma_gemm<0><<<dim3(QKV_N / 128, S_LEN / 128), 256, GEMM_SMEM>>>(h, wqkv, bqkv, nullptr, qkv,
                                                                    S_LEN, QKV_N, D_MODEL);
    // 3. ctx = attention (ALiBi + causal)
    attn_kernel<<<dim3(S_LEN / 64, NHEAD), 256>>>(qkv, alibi, ctx);
    // 4. res = x + ctx @ wo + bo
    mma_gemm<1><<<dim3(D_MODEL / 128, S_LEN / 128), 256, GEMM_SMEM>>>(ctx, wo, bo, x, res,
                                                                      S_LEN, D_MODEL, D_MODEL);
    // 5. h2 = LN2(res)
    ln_kernel<<<S_LEN, 256>>>(res, ln2g, ln2b, h2);
    // 6. mlp = gelu(h2 @ w1 + b1)
    mma_gemm<2><<<dim3(FF_DIM / 128, S_LEN / 128), 256, GEMM_SMEM>>>(h2, w1, b1, nullptr, mlp,
                                                                     S_LEN, FF_DIM, D_MODEL);
    // 7. out = res + mlp @ w2 + b2
    mma_gemm<1><<<dim3(D_MODEL / 128, S_LEN / 128), 256, GEMM_SMEM>>>(mlp, w2, b2, res, out,
                                                                      S_LEN, D_MODEL, FF_DIM);
}

// round 5
// speedup vs baseline: 2.5600x; 1.1064x over previous
#include <cuda_runtime.h>
#include <cstdint>
#include <math.h>

#define S_LEN 2048
#define D_MODEL 2048
#define NHEAD 32
#define HDIM 64
#define FF_DIM 8192
#define QKV_N (3 * D_MODEL)

// ---------------- scratch (static device globals; no allocation) ----------------
__device__ float g_h  [S_LEN * D_MODEL];
__device__ float g_qkv[S_LEN * QKV_N];
__device__ float g_ctx[S_LEN * D_MODEL];
__device__ float g_res[S_LEN * D_MODEL];
__device__ float g_h2 [S_LEN * D_MODEL];
__device__ float g_mlp[S_LEN * FF_DIM];

// ================= helpers =================
__device__ __forceinline__ uint32_t smem_u32(const void* p) {
    uint32_t a;
    asm("{ .reg .u64 t; cvta.to.shared.u64 t, %1; cvt.u32.u64 %0, t; }" : "=r"(a) : "l"(p));
    return a;
}
__device__ __forceinline__ uint32_t f2tf32(float f) {
    uint32_t u;
    asm("cvt.rna.tf32.f32 %0, %1;" : "=r"(u) : "f"(f));
    return u;
}
__device__ __forceinline__ void mma_tf32(float* d, const uint32_t* a, const uint32_t* b) {
    asm volatile(
        "mma.sync.aligned.m16n8k8.row.col.f32.tf32.tf32.f32 "
        "{%0,%1,%2,%3}, {%4,%5,%6,%7}, {%8,%9}, {%0,%1,%2,%3};"
        : "+f"(d[0]), "+f"(d[1]), "+f"(d[2]), "+f"(d[3])
        : "r"(a[0]), "r"(a[1]), "r"(a[2]), "r"(a[3]), "r"(b[0]), "r"(b[1]));
}
__device__ __forceinline__ void ldsm4(uint32_t* r, uint32_t addr) {
    asm volatile("ldmatrix.sync.aligned.m8n8.x4.shared.b16 {%0,%1,%2,%3}, [%4];"
                 : "=r"(r[0]), "=r"(r[1]), "=r"(r[2]), "=r"(r[3]) : "r"(addr));
}

// ================= tf32 tensor-core GEMM (ldmatrix + pre-converted SMEM) ========
// C[M,N] = A[M,K] @ B[K,N].  128x128 block tile, K-chunk 32, double-buffered SMEM,
// register-staged LDG pipeline. 8 warps = 4(m) x 2(n); warp tile 32x64; mma m16n8k8.
// SMEM: A [128 m][36] tf32 (row-major, 32k + pad4); B [128 n][36] tf32 (transposed).
// EPI 0: +bias   EPI 1: +bias+resid   EPI 2: gelu_exact(+bias)
#define TS_STRIDE 36
#define TILE_FLOATS (128 * TS_STRIDE)
#define GEMM_SMEM (4 * TILE_FLOATS * 4)   // 2 stages x (A + B)

template<int EPI>
__global__ __launch_bounds__(256)
void mma_gemm(const float* __restrict__ A, const float* __restrict__ B,
              const float* __restrict__ bias, const float* __restrict__ resid,
              float* __restrict__ C, int M, int N, int K)
{
    extern __shared__ float sm[];
    // layout: [stage0 A][stage0 B][stage1 A][stage1 B]
    uint32_t sbase = smem_u32(sm);

    int tid = threadIdx.x;
    int lane = tid & 31, wid = tid >> 5;
    int wm = wid & 3, wn = wid >> 2;
    int m0 = blockIdx.y * 128, n0 = blockIdx.x * 128;

    // ---- LDG register buffers ----
    float4 a_buf[4];
    float  b_buf[16];
    const int bn = tid & 127;          // B: this thread's n column
    const int bh = tid >> 7;           // B: k half (0 or 1)

    auto ldg_tile = [&](int k0) {
#pragma unroll
        for (int q = 0; q < 4; q++) {
            int idx = tid + q * 256;
            int m = idx >> 3, kq = idx & 7;
            a_buf[q] = *(const float4*)(A + (size_t)(m0 + m) * K + k0 + kq * 4);
        }
        const float* bp = B + (size_t)(k0 + bh * 16) * N + n0 + bn;
#pragma unroll
        for (int j = 0; j < 16; j++)
            b_buf[j] = bp[(size_t)j * N];
    };

    auto sts_tile = [&](int st) {
        uint32_t abase = sbase + (uint32_t)(st * 2) * TILE_FLOATS * 4;
        uint32_t bbase = abase + TILE_FLOATS * 4;
#pragma unroll
        for (int q = 0; q < 4; q++) {
            int idx = tid + q * 256;
            int m = idx >> 3, kq = idx & 7;
            uint32_t u0 = f2tf32(a_buf[q].x), u1 = f2tf32(a_buf[q].y);
            uint32_t u2 = f2tf32(a_buf[q].z), u3 = f2tf32(a_buf[q].w);
            asm volatile("st.shared.v4.b32 [%0], {%1,%2,%3,%4};"
                         :: "r"(abase + (uint32_t)(m * TS_STRIDE + kq * 4) * 4),
                            "r"(u0), "r"(u1), "r"(u2), "r"(u3) : "memory");
        }
#pragma unroll
        for (int gq = 0; gq < 4; gq++) {
            uint32_t u0 = f2tf32(b_buf[gq * 4 + 0]), u1 = f2tf32(b_buf[gq * 4 + 1]);
            uint32_t u2 = f2tf32(b_buf[gq * 4 + 2]), u3 = f2tf32(b_buf[gq * 4 + 3]);
            asm volatile("st.shared.v4.b32 [%0], {%1,%2,%3,%4};"
                         :: "r"(bbase + (uint32_t)(bn * TS_STRIDE + bh * 16 + gq * 4) * 4),
                            "r"(u0), "r"(u1), "r"(u2), "r"(u3) : "memory");
        }
    };

    float acc[2][8][4];
#pragma unroll
    for (int i = 0; i < 2; i++)
#pragma unroll
        for (int j = 0; j < 8; j++)
#pragma unroll
            for (int c = 0; c < 4; c++) acc[i][j][c] = 0.f;

    // ---- per-thread ldmatrix base offsets (col offset added per ks) ----
    int midx = lane >> 3, mrow = lane & 7;
    // A: matrices {rows+0,kb},{rows+8,kb},{rows+0,kb+4},{rows+8,kb+4}
    int a_row_off = (midx & 1) * 8 + mrow;
    int a_col_off = (midx >> 1) * 4;
    // B: matrices {nj,kb},{nj,kb+4},{nj+1,kb},{nj+1,kb+4}
    int b_row_base = wn * 64 + (midx >> 1) * 8 + mrow;
    int b_col_off = (midx & 1) * 4;

    const int T = K / 32;

    ldg_tile(0);
    sts_tile(0);
    __syncthreads();

    for (int i = 0; i < T; i++) {
        int st = i & 1;
        if (i + 1 < T) ldg_tile((i + 1) * 32);

        uint32_t abase = sbase + (uint32_t)(st * 2) * TILE_FLOATS * 4;
        uint32_t bbase = abase + TILE_FLOATS * 4;
#pragma unroll
        for (int ks = 0; ks < 4; ks++) {
            int kb = ks * 8;
            uint32_t af[2][4];
#pragma unroll
            for (int mi = 0; mi < 2; mi++) {
                int r = wm * 32 + mi * 16 + a_row_off;
                ldsm4(af[mi], abase + (uint32_t)(r * TS_STRIDE + kb + a_col_off) * 4);
            }
            uint32_t bf[8][2];
#pragma unroll
            for (int jj = 0; jj < 4; jj++) {
                uint32_t t4[4];
                int r = b_row_base + jj * 16;
                ldsm4(t4, bbase + (uint32_t)(r * TS_STRIDE + kb + b_col_off) * 4);
                bf[jj * 2 + 0][0] = t4[0]; bf[jj * 2 + 0][1] = t4[1];
                bf[jj * 2 + 1][0] = t4[2]; bf[jj * 2 + 1][1] = t4[3];
            }
#pragma unroll
            for (int mi = 0; mi < 2; mi++)
#pragma unroll
                for (int nj = 0; nj < 8; nj++)
                    mma_tf32(acc[mi][nj], af[mi], bf[nj]);
        }
        if (i + 1 < T) sts_tile(st ^ 1);
        __syncthreads();
    }

    // ---- epilogue ----
    int g = lane >> 2, t = lane & 3;
#pragma unroll
    for (int mi = 0; mi < 2; mi++) {
#pragma unroll
        for (int nj = 0; nj < 8; nj++) {
            int r0 = m0 + wm * 32 + mi * 16 + g;
            int c0 = n0 + wn * 64 + nj * 8 + 2 * t;
            float2 bv = *(const float2*)(bias + c0);
#pragma unroll
            for (int half = 0; half < 2; half++) {
                int r = r0 + half * 8;
                float vx = acc[mi][nj][half * 2 + 0] + bv.x;
                float vy = acc[mi][nj][half * 2 + 1] + bv.y;
                if (EPI == 1) {
                    float2 rv = *(const float2*)(resid + (size_t)r * N + c0);
                    vx += rv.x; vy += rv.y;
                }
                if (EPI == 2) {
                    vx = 0.5f * vx * (1.f + erff(vx * 0.70710678118654752f));
                    vy = 0.5f * vy * (1.f + erff(vy * 0.70710678118654752f));
                }
                *(float2*)(C + (size_t)r * N + c0) = make_float2(vx, vy);
            }
        }
    }
}

// ---------------- layernorm ----------------
__global__ __launch_bounds__(256)
void ln_kernel(const float* __restrict__ in, const float* __restrict__ gam,
               const float* __restrict__ bet, float* __restrict__ out)
{
    int row = blockIdx.x;
    int tid = threadIdx.x;
    const float* r = in + (size_t)row * D_MODEL;
    float v[8];
    float s = 0.f, s2 = 0.f;
#pragma unroll
    for (int i = 0; i < 8; i++) {
        v[i] = r[tid + i * 256];
        s += v[i]; s2 += v[i] * v[i];
    }
#pragma unroll
    for (int o = 16; o; o >>= 1) {
        s  += __shfl_xor_sync(0xffffffffu, s,  o);
        s2 += __shfl_xor_sync(0xffffffffu, s2, o);
    }
    __shared__ float sh0[8], sh1[8];
    if ((tid & 31) == 0) { sh0[tid >> 5] = s; sh1[tid >> 5] = s2; }
    __syncthreads();
    s = 0.f; s2 = 0.f;
#pragma unroll
    for (int i = 0; i < 8; i++) { s += sh0[i]; s2 += sh1[i]; }
    float mean = s * (1.f / D_MODEL);
    float var = s2 * (1.f / D_MODEL) - mean * mean;
    float rstd = rsqrtf(var + 1e-5f);
    float* w = out + (size_t)row * D_MODEL;
#pragma unroll
    for (int i = 0; i < 8; i++) {
        int c = tid + i * 256;
        w[c] = (v[i] - mean) * rstd * gam[c] + bet[c];
    }
}

// ---------------- flash attention with ALiBi + causal ----------------
__global__ __launch_bounds__(256)
void attn_kernel(const float* __restrict__ qkv, const float* __restrict__ alibi,
                 float* __restrict__ ctx)
{
    __shared__ float Qs[64][65];
    __shared__ float Ks[64][33];
    __shared__ float Vs[32][68];
    __shared__ float Ps[64][33];

    int tid = threadIdx.x;
    int tx = tid & 15, ty = tid >> 4;
    int q0 = blockIdx.x * 64;
    int h = blockIdx.y;

    const float* Qg = qkv + h * HDIM;
    const float* Kg = qkv + D_MODEL + h * HDIM;
    const float* Vg = qkv + 2 * D_MODEL + h * HDIM;
    const float* ab = alibi + (size_t)h * S_LEN;
    const float inv = 0.125f;

#pragma unroll
    for (int t = 0; t < 4; t++) {
        int lin = tid + t * 256;
        int row = lin >> 4;
        int c4 = (lin & 15) << 2;
        float4 v = *(const float4*)(Qg + (size_t)(q0 + row) * QKV_N + c4);
        Qs[c4 + 0][row] = v.x; Qs[c4 + 1][row] = v.y;
        Qs[c4 + 2][row] = v.z; Qs[c4 + 3][row] = v.w;
    }

    float acc[4][4];
    float m_i[4], l_i[4];
#pragma unroll
    for (int i = 0; i < 4; i++) {
        m_i[i] = -1e30f; l_i[i] = 0.f;
#pragma unroll
        for (int j = 0; j < 4; j++) acc[i][j] = 0.f;
    }

    for (int k0 = 0; k0 < q0 + 64; k0 += 32) {
        __syncthreads();
#pragma unroll
        for (int t = 0; t < 2; t++) {
            int lin = tid + t * 256;
            int row = lin >> 4;
            int c4 = (lin & 15) << 2;
            float4 v = *(const float4*)(Kg + (size_t)(k0 + row) * QKV_N + c4);
            Ks[c4 + 0][row] = v.x; Ks[c4 + 1][row] = v.y;
            Ks[c4 + 2][row] = v.z; Ks[c4 + 3][row] = v.w;
            float4 w = *(const float4*)(Vg + (size_t)(k0 + row) * QKV_N + c4);
            *(float4*)(&Vs[row][c4]) = w;
        }
        __syncthreads();

        float s[4][2];
#pragma unroll
        for (int i = 0; i < 4; i++) { s[i][0] = 0.f; s[i][1] = 0.f; }
#pragma unroll
        for (int d = 0; d < 64; d++) {
            float a0 = Qs[d][ty * 4 + 0], a1 = Qs[d][ty * 4 + 1];
            float a2 = Qs[d][ty * 4 + 2], a3 = Qs[d][ty * 4 + 3];
            float b0 = Ks[d][tx * 2 + 0], b1 = Ks[d][tx * 2 + 1];
            s[0][0] = fmaf(a0, b0, s[0][0]); s[0][1] = fmaf(a0, b1, s[0][1]);
            s[1][0] = fmaf(a1, b0, s[1][0]); s[1][1] = fmaf(a1, b1, s[1][1]);
            s[2][0] = fmaf(a2, b0, s[2][0]); s[2][1] = fmaf(a2, b1, s[2][1]);
            s[3][0] = fmaf(a3, b0, s[3][0]); s[3][1] = fmaf(a3, b1, s[3][1]);
        }

        float rmax[4];
#pragma unroll
        for (int i = 0; i < 4; i++) {
            int qg = q0 + ty * 4 + i;
            float mx = -1e30f;
#pragma unroll
            for (int j = 0; j < 2; j++) {
                int kg = k0 + tx * 2 + j;
                float val = (kg <= qg) ? (s[i][j] + ab[kg]) * inv : -1e30f;
                s[i][j] = val;
                mx = fmaxf(mx, val);
            }
            rmax[i] = mx;
        }
#pragma unroll
        for (int o = 1; o < 16; o <<= 1) {
#pragma unroll
            for (int i = 0; i < 4; i++)
                rmax[i] = fmaxf(rmax[i], __shfl_xor_sync(0xffffffffu, rmax[i], o));
        }

#pragma unroll
        for (int i = 0; i < 4; i++) {
            float mnew = fmaxf(m_i[i], rmax[i]);
            float sc = expf(m_i[i] - mnew);
            float p0 = expf(s[i][0] - mnew);
            float p1 = expf(s[i][1] - mnew);
            Ps[ty * 4 + i][tx * 2 + 0] = p0;
            Ps[ty * 4 + i][tx * 2 + 1] = p1;
            float ps = p0 + p1;
#pragma unroll
            for (int o = 1; o < 16; o <<= 1)
                ps += __shfl_xor_sync(0xffffffffu, ps, o);
            l_i[i] = l_i[i] * sc + ps;
            m_i[i] = mnew;
            acc[i][0] *= sc; acc[i][1] *= sc; acc[i][2] *= sc; acc[i][3] *= sc;
        }
        __syncthreads();

#pragma unroll
        for (int kk = 0; kk < 32; kk++) {
            float p0 = Ps[ty * 4 + 0][kk], p1 = Ps[ty * 4 + 1][kk];
            float p2 = Ps[ty * 4 + 2][kk], p3 = Ps[ty * 4 + 3][kk];
            float v0 = Vs[kk][tx * 4 + 0], v1 = Vs[kk][tx * 4 + 1];
            float v2 = Vs[kk][tx * 4 + 2], v3 = Vs[kk][tx * 4 + 3];
            acc[0][0] = fmaf(p0, v0, acc[0][0]); acc[0][1] = fmaf(p0, v1, acc[0][1]);
            acc[0][2] = fmaf(p0, v2, acc[0][2]); acc[0][3] = fmaf(p0, v3, acc[0][3]);
            acc[1][0] = fmaf(p1, v0, acc[1][0]); acc[1][1] = fmaf(p1, v1, acc[1][1]);
            acc[1][2] = fmaf(p1, v2, acc[1][2]); acc[1][3] = fmaf(p1, v3, acc[1][3]);
            acc[2][0] = fmaf(p2, v0, acc[2][0]); acc[2][1] = fmaf(p2, v1, acc[2][1]);
            acc[2][2] = fmaf(p2, v2, acc[2][2]); acc[2][3] = fmaf(p2, v3, acc[2][3]);
            acc[3][0] = fmaf(p3, v0, acc[3][0]); acc[3][1] = fmaf(p3, v1, acc[3][1]);
            acc[3][2] = fmaf(p3, v2, acc[3][2]); acc[3][3] = fmaf(p3, v3, acc[3][3]);
        }
    }

#pragma unroll
    for (int i = 0; i < 4; i++) {
        float r = 1.f / l_i[i];
        int qg = q0 + ty * 4 + i;
        float* w = ctx + (size_t)qg * D_MODEL + h * HDIM + tx * 4;
        w[0] = acc[i][0] * r; w[1] = acc[i][1] * r;
        w[2] = acc[i][2] * r; w[3] = acc[i][3] * r;
    }
}

// ---------------- launch ----------------
extern "C" void kernel_launch(void* const* d_in, const int* in_sizes, int n_in,
                              void* d_out, int out_size)
{
    const float* x     = (const float*)d_in[0];
    const float* alibi = (const float*)d_in[1];
    const float* ln1g  = (const float*)d_in[3];
    const float* ln1b  = (const float*)d_in[4];
    const float* ln2g  = (const float*)d_in[5];
    const float* ln2b  = (const float*)d_in[6];
    const float* wqkv  = (const float*)d_in[7];
    const float* bqkv  = (const float*)d_in[8];
    const float* wo    = (const float*)d_in[9];
    const float* bo    = (const float*)d_in[10];
    const float* w1    = (const float*)d_in[11];
    const float* b1    = (const float*)d_in[12];
    const float* w2    = (const float*)d_in[13];
    const float* b2    = (const float*)d_in[14];
    float* out = (float*)d_out;

    float *h, *qkv, *ctx, *res, *h2, *mlp;
    cudaGetSymbolAddress((void**)&h,   g_h);
    cudaGetSymbolAddress((void**)&qkv, g_qkv);
    cudaGetSymbolAddress((void**)&ctx, g_ctx);
    cudaGetSymbolAddress((void**)&res, g_res);
    cudaGetSymbolAddress((void**)&h2,  g_h2);
    cudaGetSymbolAddress((void**)&mlp, g_mlp);

    cudaFuncSetAttribute(mma_gemm<0>, cudaFuncAttributeMaxDynamicSharedMemorySize, GEMM_SMEM);
    cudaFuncSetAttribute(mma_gemm<1>, cudaFuncAttributeMaxDynamicSharedMemorySize, GEMM_SMEM);
    cudaFuncSetAttribute(mma_gemm<2>, cudaFuncAttributeMaxDynamicSharedMemorySize, GEMM_SMEM);

    // 1. h = LN1(x)
    ln_kernel<<<S_LEN, 256>>>(x, ln1g, ln1b, h);
    // 2. qkv = h @ wqkv + bqkv
    mma_gemm<0><<<dim3(QKV_N / 128, S_LEN / 128), 256, GEMM_SMEM>>>(h, wqkv, bqkv, nullptr, qkv,
                                                                    S_LEN, QKV_N, D_MODEL);
    // 3. ctx = attention (ALiBi + causal)
    attn_kernel<<<dim3(S_LEN / 64, NHEAD), 256>>>(qkv, alibi, ctx);
    // 4. res = x + ctx @ wo + bo
    mma_gemm<1><<<dim3(D_MODEL / 128, S_LEN / 128), 256, GEMM_SMEM>>>(ctx, wo, bo, x, res,
                                                                      S_LEN, D_MODEL, D_MODEL);
    // 5. h2 = LN2(res)
    ln_kernel<<<S_LEN, 256>>>(res, ln2g, ln2b, h2);
    // 6. mlp = gelu(h2 @ w1 + b1)
    mma_gemm<2><<<dim3(FF_DIM / 128, S_LEN / 128), 256, GEMM_SMEM>>>(h2, w1, b1, nullptr, mlp,
                                                                     S_LEN, FF_DIM, D_MODEL);
    // 7. out = res + mlp @ w2 + b2
    mma_gemm<1><<<dim3(D_MODEL / 128, S_LEN / 128), 256, GEMM_SMEM>>>(mlp, w2, b2, res, out,
                                                                      S_LEN, D_MODEL, FF_DIM);
}